// round 16
// baseline (speedup 1.0000x reference)
#include <cuda_runtime.h>

// StripePolynomial2d — GB300 sm_103a, round 13
//
// = R9b (best, 23.3us E2E) with ONE change: the CTA's x working set (24KB)
// staged into shared via cp.async.cg (L1-bypassing, 16B granules, 6/thread)
// at kernel start; c-loop reads x from shared (LDS 29cyc) instead of global
// (L2/DRAM 234-600cyc). Removes the 3 long-scoreboard stalls per thread that
// R9b..R12 proved were the binding constraint (instruction cuts didn't move
// dur; all variants latency-bound at issue~30%).

#define NW 129
#define PLANE (512*512)

typedef unsigned long long u64;

__device__ __forceinline__ u64 pk(float a, float b) {
    u64 r;
    asm("mov.b64 %0, {%1, %2};" : "=l"(r) : "f"(a), "f"(b));
    return r;
}
__device__ __forceinline__ u64 ffma2(u64 a, u64 b, u64 c) {
    u64 d;
    asm("fma.rn.f32x2 %0, %1, %2, %3;" : "=l"(d) : "l"(a), "l"(b), "l"(c));
    return d;
}
__device__ __forceinline__ u64 fadd2(u64 a, u64 b) {
    u64 d;
    asm("add.rn.f32x2 %0, %1, %2;" : "=l"(d) : "l"(a), "l"(b));
    return d;
}
__device__ __forceinline__ void upk(u64 v, float& lo, float& hi) {
    asm("mov.b64 {%0, %1}, %2;" : "=f"(lo), "=f"(hi) : "l"(v));
}
__device__ __forceinline__ u64 dup_bits(float v) {
    unsigned int b = __float_as_uint(v);
    return ((u64)b << 32) | (u64)b;
}

// table per (g,c,seg,o): 6 u64 {A0,A1,A2,G1,G2,pad}, lane-dup (83KB, L1-resident)
__device__ u64 g_tab[1728 * 6];
// prologue tables: (pad, d0, int_bits(seg*3), pad)
__device__ float4 g_pre0[512];    // index w        (stripe group 0)
__device__ float4 g_pre1[1023];   // index w+h (g1) and w-h+511 (g2)

__global__ void build_kernel(const float* __restrict__ Wt)
{
    int e = blockIdx.x * 256 + threadIdx.x;

    if (e < 1728) {
        int o = e % 3;
        int s = (e / 3) & 63;
        int c = (e / 192) % 3;
        int g = e / 576;

        auto coef_at = [&](int seg, float& a0, float& a1, float& a2) {
            int k = 2 * seg;
            float w0, w1, w2;
            if (g == 0) {
                const float* p0 = Wt + ((0 * 3 + o) * 3 + c) * NW + k;
                const float* p1 = Wt + ((1 * 3 + o) * 3 + c) * NW + k;
                w0 = p0[0] + p1[0];
                w1 = p0[1] + p1[1];
                w2 = p0[2] + p1[2];
            } else {
                const float* p = Wt + (((g + 1) * 3 + o) * 3 + c) * NW + k;
                w0 = p[0]; w1 = p[1]; w2 = p[2];
            }
            a0 = 0.25f * w1;
            a1 = 0.25f * (0.5f * (w2 - w0));
            a2 = 0.25f * (0.5f * (w0 + w2) - w1);
        };

        float a0, a1, a2;
        coef_at(s, a0, a1, a2);

        float g1 = 0.0f, g2 = 0.0f;
        if (s < 63) {
            float b0, b1, b2;
            coef_at(s + 1, b0, b1, b2);
            // B(u) = P_{s+1}(u-2) - P_s(u), B(1)=0 (continuity)
            float c1p = (b1 - 4.0f * b2) - a1;
            float c2p = b2 - a2;
            g2 = 0.5f * c2p;              // pre-halved: r' = 2*relu
            g1 = 0.5f * (c1p + c2p);
        }

        u64* dst = g_tab + e * 6;
        dst[0] = dup_bits(a0);
        dst[1] = dup_bits(a1);
        dst[2] = dup_bits(a2);
        dst[3] = dup_bits(g1);
        dst[4] = dup_bits(g2);
        dst[5] = 0ULL;
        return;
    }

    // prologue tables (fp64 once, mirrors reference float64 grid math)
    const double RATIO = 512.0 / 513.0;
    float bb;
    float4* dst;
    if (e < 1728 + 512) {
        int i = e - 1728;
        bb = (float)(((double)i * RATIO / 511.0 - 0.5) * 512.0) * 0.125f + 32.0f;
        dst = &g_pre0[i];
    } else if (e < 1728 + 512 + 1023) {
        int i = e - (1728 + 512);
        bb = (float)(((double)i * RATIO / 1022.0 - 0.5) * 512.0) * 0.125f + 32.0f;
        dst = &g_pre1[i];
    } else {
        return;
    }
    float s0f = fminf(fmaxf(floorf(bb), 0.0f), 63.0f);
    float fb  = bb - s0f;                 // exact
    float d0  = 2.0f * fb - 1.0f;
    int   s3  = (int)s0f * 3;
    *dst = make_float4(0.0f, d0, __int_as_float(s3), 0.0f);
}

__global__ __launch_bounds__(256, 3)
void stripe_poly_kernel(const float* __restrict__ x,
                        float* __restrict__ out)
{
    __shared__ float xs[24 * 256];   // 24KB: plane-major [b*3+c][tid]

    int tid = threadIdx.x;

    // ---- stage x into shared: 6 x cp.async.cg 16B per thread (L1-bypass) ----
    {
        const char* xbase = (const char*)x + (size_t)blockIdx.x * 1024;
        unsigned int xs_base = (unsigned int)__cvta_generic_to_shared(xs);
        #pragma unroll
        for (int i = 0; i < 6; i++) {
            int k     = tid + 256 * i;        // chunk id 0..1535
            int plane = k >> 6;               // 0..23  (= b*3+c)
            int off   = (k & 63) << 4;        // byte offset within 1KB slice
            const char* src = xbase + (size_t)plane * (PLANE * 4) + off;
            unsigned int dst = xs_base + plane * 1024 + off;
            asm volatile("cp.async.cg.shared.global [%0], [%1], 16;"
                         :: "r"(dst), "l"(src) : "memory");
        }
        asm volatile("cp.async.commit_group;" ::: "memory");
    }

    int pid = blockIdx.x * 256 + tid;
    int w = pid >> 9;
    int h = pid & 511;

    // table-driven prologue (overlaps the async copies)
    float4 P0 = g_pre0[w];
    float4 P1 = g_pre1[w + h];
    float4 P2 = g_pre1[w - h + 511];

    u64 dd2g[3];
    int idxg[3];
    dd2g[0] = pk(P0.y, P0.y); idxg[0] =        __float_as_int(P0.z);
    dd2g[1] = pk(P1.y, P1.y); idxg[1] = 576  + __float_as_int(P1.z);
    dd2g[2] = pk(P2.y, P2.y); idxg[2] = 1152 + __float_as_int(P2.z);

    const u64 Q2   = pk(0.25f, 0.25f);
    const u64 M1   = pk(-1.0f, -1.0f);
    const u64 ABSM = 0x7fffffff7fffffffULL;

    u64 acc2[4][3];
    #pragma unroll
    for (int p = 0; p < 4; p++)
        #pragma unroll
        for (int o = 0; o < 3; o++)
            acc2[p][o] = 0ULL;

    asm volatile("cp.async.wait_group 0;" ::: "memory");
    __syncthreads();

    #pragma unroll
    for (int c = 0; c < 3; c++) {
        float xv[8];
        #pragma unroll
        for (int b = 0; b < 8; b++)
            xv[b] = xs[(b * 3 + c) * 256 + tid];
        u64 xv2[4];
        #pragma unroll
        for (int p = 0; p < 4; p++)
            xv2[p] = pk(xv[2 * p], xv[2 * p + 1]);

        #pragma unroll
        for (int g = 0; g < 3; g++) {
            const u64* tb = g_tab + (u64)(idxg[g] + c * 192) * 6;

            // u = 0.25x + d0 ; r' = (u-1) + |u-1| = 2*relu(u-1)
            u64 u2[4], r2[4];
            u64 dd2 = dd2g[g];
            #pragma unroll
            for (int p = 0; p < 4; p++) {
                u2[p] = ffma2(Q2, xv2[p], dd2);
                u64 t = fadd2(u2[p], M1);
                r2[p] = fadd2(t, t & ABSM);
            }

            #pragma unroll
            for (int o = 0; o < 3; o++) {
                const ulonglong2* tp = (const ulonglong2*)(tb + o * 6);
                ulonglong2 v0 = __ldg(tp);       // A0, A1
                ulonglong2 v1 = __ldg(tp + 1);   // A2, G1
                ulonglong2 v2 = __ldg(tp + 2);   // G2, pad
                u64 A0 = v0.x, A1 = v0.y, A2 = v1.x, G1 = v1.y, G2 = v2.x;
                #pragma unroll
                for (int p = 0; p < 4; p++) {
                    u64 hh = ffma2(G2, u2[p], G1);
                    u64 t  = ffma2(A2, u2[p], A1);
                    t      = ffma2(t, u2[p], A0);
                    acc2[p][o] = fadd2(acc2[p][o], t);
                    acc2[p][o] = ffma2(r2[p], hh, acc2[p][o]);
                }
            }
        }
    }

    #pragma unroll
    for (int p = 0; p < 4; p++)
        #pragma unroll
        for (int o = 0; o < 3; o++) {
            float lo, hi;
            upk(acc2[p][o], lo, hi);
            out[((2 * p)     * 3 + o) * PLANE + pid] = lo;
            out[((2 * p + 1) * 3 + o) * PLANE + pid] = hi;
        }
}

extern "C" void kernel_launch(void* const* d_in, const int* in_sizes, int n_in,
                              void* d_out, int out_size)
{
    const float* x  = (const float*)d_in[0];
    const float* Wt = (const float*)d_in[1];
    if (n_in >= 2 && in_sizes[0] == 4644) {
        Wt = (const float*)d_in[0];
        x  = (const float*)d_in[1];
    }
    float* out = (float*)d_out;

    build_kernel<<<13, 256>>>(Wt);     // 1728 table entries + 512 + 1023 prologue
    stripe_poly_kernel<<<(512 * 512) / 256, 256>>>(x, out);
}

// round 17
// speedup vs baseline: 1.3563x; 1.3563x over previous
#include <cuda_runtime.h>

// StripePolynomial2d — GB300 sm_103a, round 14: pixel-pair lanes
//
// f32x2 lanes now hold (pixel h, pixel h+1) instead of (batch pair). Adjacent
// pixels share one reference segment (base delta 0.063 seg; relu-correction
// formula is exact over [s0, s0+1], worst-case t=1.375<3), so:
//  - x loads are LDG.64 of adjacent pixels (no pk movs), 12/thread
//  - lane-dup table loads serve BOTH pixels (per-pixel table loads halved)
//  - stores are STG.64 from packed accumulators (no upk)
// 4 batches/thread via grid.y=2; grid stays 1024 blocks (same warp supply).
// t-rebased coefficients + sA0 hoist (R12-proven algebra).

#define NW 129
#define PLANE (512*512)

typedef unsigned long long u64;

__device__ __forceinline__ u64 pk(float a, float b) {
    u64 r;
    asm("mov.b64 %0, {%1, %2};" : "=l"(r) : "f"(a), "f"(b));
    return r;
}
__device__ __forceinline__ u64 ffma2(u64 a, u64 b, u64 c) {
    u64 d;
    asm("fma.rn.f32x2 %0, %1, %2, %3;" : "=l"(d) : "l"(a), "l"(b), "l"(c));
    return d;
}
__device__ __forceinline__ u64 fadd2(u64 a, u64 b) {
    u64 d;
    asm("add.rn.f32x2 %0, %1, %2;" : "=l"(d) : "l"(a), "l"(b));
    return d;
}
__device__ __forceinline__ u64 dup_bits(float v) {
    unsigned int b = __float_as_uint(v);
    return ((u64)b << 32) | (u64)b;
}

// table per (g,c,seg,o): 6 u64 {A0',A1',A2',G1',G2',pad}, t-rebased, lane-dup
// idx = ((g*3+c)*64+seg)*3+o  (R9b addressing, 83KB, L1-resident)
__device__ u64 g_tab[1728 * 6];
// prologue tables: (base_in_segments, d0-1, int_bits(seg*3), 0)
__device__ float4 g_pre0[512];    // index w        (stripe group 0)
__device__ float4 g_pre1[1023];   // index w+h (g1) and w-h+511 (g2)

__global__ void build_kernel(const float* __restrict__ Wt)
{
    int e = blockIdx.x * 256 + threadIdx.x;

    if (e < 1728) {
        int o = e % 3;
        int s = (e / 3) & 63;
        int c = (e / 192) % 3;
        int g = e / 576;

        auto coef_at = [&](int seg, float& a0, float& a1, float& a2) {
            int k = 2 * seg;
            float w0, w1, w2;
            if (g == 0) {
                const float* p0 = Wt + ((0 * 3 + o) * 3 + c) * NW + k;
                const float* p1 = Wt + ((1 * 3 + o) * 3 + c) * NW + k;
                w0 = p0[0] + p1[0];
                w1 = p0[1] + p1[1];
                w2 = p0[2] + p1[2];
            } else {
                const float* p = Wt + (((g + 1) * 3 + o) * 3 + c) * NW + k;
                w0 = p[0]; w1 = p[1]; w2 = p[2];
            }
            a0 = 0.25f * w1;
            a1 = 0.25f * (0.5f * (w2 - w0));
            a2 = 0.25f * (0.5f * (w0 + w2) - w1);
        };

        float a0, a1, a2;
        coef_at(s, a0, a1, a2);

        float g1 = 0.0f, g2 = 0.0f;
        if (s < 63) {
            float b0, b1, b2;
            coef_at(s + 1, b0, b1, b2);
            // B(u) = P_{s+1}(u-2) - P_s(u), B(1)=0 (continuity)
            float c1p = (b1 - 4.0f * b2) - a1;
            float c2p = b2 - a2;
            g2 = 0.5f * c2p;              // pre-halved: r' = 2*relu
            g1 = 0.5f * (c1p + c2p);
        }

        // rebase to t = u-1: A'(t) = A(t+1), hh'(t) = hh(t+1)
        u64* dst = g_tab + e * 6;
        dst[0] = dup_bits(a0 + a1 + a2);
        dst[1] = dup_bits(a1 + 2.0f * a2);
        dst[2] = dup_bits(a2);
        dst[3] = dup_bits(g1 + g2);
        dst[4] = dup_bits(g2);
        dst[5] = 0ULL;
        return;
    }

    // prologue tables (fp64 once, mirrors reference float64 grid math)
    const double RATIO = 512.0 / 513.0;
    float bb;
    float4* dst;
    if (e < 1728 + 512) {
        int i = e - 1728;
        bb = (float)(((double)i * RATIO / 511.0 - 0.5) * 512.0) * 0.125f + 32.0f;
        dst = &g_pre0[i];
    } else if (e < 1728 + 512 + 1023) {
        int i = e - (1728 + 512);
        bb = (float)(((double)i * RATIO / 1022.0 - 0.5) * 512.0) * 0.125f + 32.0f;
        dst = &g_pre1[i];
    } else {
        return;
    }
    float s0f = fminf(fmaxf(floorf(bb), 0.0f), 63.0f);
    float fb  = bb - s0f;                 // exact
    float dm1 = 2.0f * fb - 2.0f;         // t = 0.25x + dm1
    int   s3  = (int)s0f * 3;
    *dst = make_float4(bb, dm1, __int_as_float(s3), 0.0f);
}

__global__ __launch_bounds__(256, 3)
void stripe_poly_kernel(const float* __restrict__ x,
                        float* __restrict__ out)
{
    int tid  = threadIdx.x;
    int tpix = blockIdx.x * 256 + tid;      // pixel-pair index
    int w    = tpix >> 8;
    int h0   = (tpix & 255) << 1;           // pixel A = (w,h0), B = (w,h0+1)
    int b0   = blockIdx.y * 4;

    // prologue: per-g reference segment = smaller-base side of the pair
    float4 P0 = g_pre0[w];
    float4 Pa = g_pre1[w + h0];             // g1 ref (pixel A, smaller base)
    float4 Pb = g_pre1[w + h0 + 1];
    float4 Qa = g_pre1[w - h0 + 511];       // pixel A (larger base for g2)
    float4 Qb = g_pre1[w - h0 + 510];       // g2 ref (pixel B, smaller base)

    u64 dm2g[3];
    int idxg[3];
    dm2g[0] = pk(P0.y, P0.y);
    idxg[0] = __float_as_int(P0.z);
    dm2g[1] = pk(Pa.y, Pa.y + 2.0f * (Pb.x - Pa.x));
    idxg[1] = 576 + __float_as_int(Pa.z);
    dm2g[2] = pk(Qb.y + 2.0f * (Qa.x - Qb.x), Qb.y);
    idxg[2] = 1152 + __float_as_int(Qb.z);

    const u64 Q2   = pk(0.25f, 0.25f);
    const u64 ABSM = 0x7fffffff7fffffffULL;

    u64 acc2[4][3];
    #pragma unroll
    for (int b = 0; b < 4; b++)
        #pragma unroll
        for (int o = 0; o < 3; o++)
            acc2[b][o] = 0ULL;
    u64 sA0[3] = {0ULL, 0ULL, 0ULL};

    #pragma unroll
    for (int c = 0; c < 3; c++) {
        // x loads: one LDG.64 per batch = (pixelA, pixelB) packed by memory
        u64 xv2[4];
        #pragma unroll
        for (int b = 0; b < 4; b++)
            xv2[b] = __ldg((const u64*)(x + ((b0 + b) * 3 + c) * PLANE) + tpix);

        #pragma unroll
        for (int g = 0; g < 3; g++) {
            const u64* tb = g_tab + (u64)(idxg[g] + c * 192) * 6;

            // t = 0.25x + (d0-1) per lane ; r' = t + |t| = 2*relu(t)
            u64 t2[4], r2[4];
            u64 dm2 = dm2g[g];
            #pragma unroll
            for (int b = 0; b < 4; b++) {
                t2[b] = ffma2(Q2, xv2[b], dm2);
                r2[b] = fadd2(t2[b], t2[b] & ABSM);
            }

            #pragma unroll
            for (int o = 0; o < 3; o++) {
                const ulonglong2* tp = (const ulonglong2*)(tb + o * 6);
                ulonglong2 v0 = __ldg(tp);       // A0', A1'
                ulonglong2 v1 = __ldg(tp + 1);   // A2', G1'
                ulonglong2 v2 = __ldg(tp + 2);   // G2', pad
                u64 A0 = v0.x, A1 = v0.y, A2 = v1.x, G1 = v1.y, G2 = v2.x;
                sA0[o] = fadd2(sA0[o], A0);
                #pragma unroll
                for (int b = 0; b < 4; b++) {
                    u64 s1 = ffma2(A2, t2[b], A1);
                    acc2[b][o] = ffma2(t2[b], s1, acc2[b][o]);
                    u64 hh = ffma2(G2, t2[b], G1);
                    acc2[b][o] = ffma2(r2[b], hh, acc2[b][o]);
                }
            }
        }
    }

    // packed stores: one STG.64 per (batch,o) covers both pixels
    #pragma unroll
    for (int b = 0; b < 4; b++)
        #pragma unroll
        for (int o = 0; o < 3; o++)
            *((u64*)(out + ((b0 + b) * 3 + o) * PLANE) + tpix) =
                fadd2(acc2[b][o], sA0[o]);
}

extern "C" void kernel_launch(void* const* d_in, const int* in_sizes, int n_in,
                              void* d_out, int out_size)
{
    const float* x  = (const float*)d_in[0];
    const float* Wt = (const float*)d_in[1];
    if (n_in >= 2 && in_sizes[0] == 4644) {
        Wt = (const float*)d_in[0];
        x  = (const float*)d_in[1];
    }
    float* out = (float*)d_out;

    build_kernel<<<13, 256>>>(Wt);     // 1728 table entries + 512 + 1023 prologue
    dim3 grid(512, 2);                 // 512 pixel-pair blocks x 2 batch halves
    stripe_poly_kernel<<<grid, 256>>>(x, out);
}